// round 4
// baseline (speedup 1.0000x reference)
#include <cuda_runtime.h>
#include <math.h>

// Problem constants
#define T_  1024
#define B_  4
#define E_  512
#define H_  8
#define D_  64
#define P_  64
#define K2_ 128           // 2*P
#define M_  (T_*B_)       // 4096 rows
#define EPS_ 1e-6f

// ---------------------------------------------------------------------------
// Static device scratch (no allocations allowed)
// ---------------------------------------------------------------------------
__device__ float g_q   [M_ * E_];        // 8 MB
__device__ float g_k   [M_ * E_];        // 8 MB
__device__ float g_v   [M_ * E_];        // 8 MB
__device__ float g_pq  [M_ * H_ * K2_];  // 16 MB
__device__ float g_pk  [M_ * H_ * K2_];  // 16 MB
__device__ float g_attn[M_ * E_];        // 8 MB

// ---------------------------------------------------------------------------
// Packed f32x2 helpers (Blackwell sm_103a)
// ---------------------------------------------------------------------------
__device__ __forceinline__ unsigned long long pack_f32x2(float lo, float hi) {
    unsigned long long r;
    asm("mov.b64 %0, {%1, %2};" : "=l"(r) : "f"(lo), "f"(hi));
    return r;
}
__device__ __forceinline__ void unpack_f32x2(float& lo, float& hi, unsigned long long v) {
    asm("mov.b64 {%0, %1}, %2;" : "=f"(lo), "=f"(hi) : "l"(v));
}
__device__ __forceinline__ unsigned long long fma_f32x2(unsigned long long a,
                                                        unsigned long long b,
                                                        unsigned long long c) {
    unsigned long long d;
    asm("fma.rn.f32x2 %0, %1, %2, %3;" : "=l"(d) : "l"(a), "l"(b), "l"(c));
    return d;
}

// ---------------------------------------------------------------------------
// GEMM with bias: C[M,N] = A[M,K] @ W[N,K]^T + bias[N]
// M=4096, N=K=512.  Tile 128x128, BK=16, 256 threads, 8x8 microtile via
// packed fma.rn.f32x2 (acc pairs along N).  Register double-buffer: global
// loads for k0+BK issue BEFORE the compute of k0, hiding LDG latency.
// blockIdx.z selects (W, bias, C) so QKV runs as ONE launch (384 CTAs).
// ---------------------------------------------------------------------------
__global__ __launch_bounds__(256)
void gemm_bias_kernel(const float* __restrict__ A,
                      const float* __restrict__ W0, const float* __restrict__ W1,
                      const float* __restrict__ W2,
                      const float* __restrict__ b0p, const float* __restrict__ b1p,
                      const float* __restrict__ b2p,
                      float* __restrict__ C0, float* __restrict__ C1,
                      float* __restrict__ C2)
{
    constexpr int Kd = 512, BM = 128, BK = 16;
    __shared__ float As[BK][BM + 4];   // row pitch 132 floats (16B multiple)
    __shared__ float Bs[BK][BM + 4];

    const int z = blockIdx.z;
    const float* Bw   = (z == 0) ? W0  : (z == 1) ? W1  : W2;
    const float* bias = (z == 0) ? b0p : (z == 1) ? b1p : b2p;
    float*       C    = (z == 0) ? C0  : (z == 1) ? C1  : C2;

    const int tid  = threadIdx.x;
    const int bm   = blockIdx.x * BM;
    const int bn   = blockIdx.y * BM;
    const int lrow = tid >> 2;          // 0..63
    const int lcol = (tid & 3) << 2;    // 0,4,8,12
    const int tx   = tid & 15;
    const int ty   = tid >> 4;

    const float* Ap0 = A  + (size_t)(bm + lrow     ) * Kd + lcol;
    const float* Ap1 = A  + (size_t)(bm + lrow + 64) * Kd + lcol;
    const float* Wp0 = Bw + (size_t)(bn + lrow     ) * Kd + lcol;
    const float* Wp1 = Bw + (size_t)(bn + lrow + 64) * Kd + lcol;

    // acc2[i][j4] packs columns (2*j4, 2*j4+1) for row i
    unsigned long long acc2[8][4];
#pragma unroll
    for (int i = 0; i < 8; i++)
#pragma unroll
        for (int j = 0; j < 4; j++) acc2[i][j] = 0ull;

    // prologue: prefetch k0 = 0
    float4 ra0 = *(const float4*)(Ap0);
    float4 ra1 = *(const float4*)(Ap1);
    float4 rw0 = *(const float4*)(Wp0);
    float4 rw1 = *(const float4*)(Wp1);

    for (int k0 = 0; k0 < Kd; k0 += BK) {
        __syncthreads();   // previous compute done reading smem
        As[lcol + 0][lrow]      = ra0.x; As[lcol + 1][lrow]      = ra0.y;
        As[lcol + 2][lrow]      = ra0.z; As[lcol + 3][lrow]      = ra0.w;
        As[lcol + 0][lrow + 64] = ra1.x; As[lcol + 1][lrow + 64] = ra1.y;
        As[lcol + 2][lrow + 64] = ra1.z; As[lcol + 3][lrow + 64] = ra1.w;
        Bs[lcol + 0][lrow]      = rw0.x; Bs[lcol + 1][lrow]      = rw0.y;
        Bs[lcol + 2][lrow]      = rw0.z; Bs[lcol + 3][lrow]      = rw0.w;
        Bs[lcol + 0][lrow + 64] = rw1.x; Bs[lcol + 1][lrow + 64] = rw1.y;
        Bs[lcol + 2][lrow + 64] = rw1.z; Bs[lcol + 3][lrow + 64] = rw1.w;
        __syncthreads();

        // prefetch next k-slab; latency hidden under the 16-kk compute below
        if (k0 + BK < Kd) {
            const int kn = k0 + BK;
            ra0 = *(const float4*)(Ap0 + kn);
            ra1 = *(const float4*)(Ap1 + kn);
            rw0 = *(const float4*)(Wp0 + kn);
            rw1 = *(const float4*)(Wp1 + kn);
        }

#pragma unroll
        for (int kk = 0; kk < BK; kk++) {
            float a[8];
            *(float4*)(a)     = *(const float4*)&As[kk][ty * 8];
            *(float4*)(a + 4) = *(const float4*)&As[kk][ty * 8 + 4];
            // b pairs read directly as packed 64-bit (16B-aligned smem)
            ulonglong2 bp01 = *(const ulonglong2*)&Bs[kk][tx * 8];
            ulonglong2 bp23 = *(const ulonglong2*)&Bs[kk][tx * 8 + 4];
            unsigned long long bp[4] = { bp01.x, bp01.y, bp23.x, bp23.y };
#pragma unroll
            for (int i = 0; i < 8; i++) {
                const unsigned long long ap = pack_f32x2(a[i], a[i]);
#pragma unroll
                for (int j = 0; j < 4; j++)
                    acc2[i][j] = fma_f32x2(ap, bp[j], acc2[i][j]);
            }
        }
    }

    float bb[8];
#pragma unroll
    for (int j = 0; j < 8; j++) bb[j] = bias[bn + tx * 8 + j];

#pragma unroll
    for (int i = 0; i < 8; i++) {
        float o[8];
#pragma unroll
        for (int j = 0; j < 4; j++)
            unpack_f32x2(o[2 * j], o[2 * j + 1], acc2[i][j]);
#pragma unroll
        for (int j = 0; j < 8; j++) o[j] += bb[j];
        float* cp = C + (size_t)(bm + ty * 8 + i) * 512 + bn + tx * 8;
        *(float4*)cp       = make_float4(o[0], o[1], o[2], o[3]);
        *(float4*)(cp + 4) = make_float4(o[4], o[5], o[6], o[7]);
    }
}

// ---------------------------------------------------------------------------
// phi: [M,H,D] -> [M,H,2P].  Normalize over D, project with rm[h] (P x D),
// emit [sin(proj), cos(proj)] * P^{-1/2}.
// grid (M/64, H, 2): z selects (q -> pq) or (k -> pk).
// ---------------------------------------------------------------------------
__global__ __launch_bounds__(256)
void phi_kernel(const float* __restrict__ rm)
{
    __shared__ float rm_s[P_][D_ + 1];  // pad -> conflict-free rm_s[p][dd]
    __shared__ float xs[8][D_];

    const int tid = threadIdx.x;
    const int h   = blockIdx.y;
    const float* src = (blockIdx.z == 0) ? g_q  : g_k;
    float*       dst = (blockIdx.z == 0) ? g_pq : g_pk;

    for (int i = tid; i < P_ * D_; i += 256)
        rm_s[i >> 6][i & 63] = rm[(size_t)h * P_ * D_ + i];
    __syncthreads();

    const int w    = tid >> 5;
    const int lane = tid & 31;
    const int base = blockIdx.x * 64;

    for (int it = 0; it < 8; it++) {
        const int r = base + it * 8 + w;
        const float* xr = src + ((size_t)r * H_ + h) * D_;
        float x0 = xr[lane], x1 = xr[lane + 32];

        float ss = x0 * x0 + x1 * x1;
#pragma unroll
        for (int off = 16; off; off >>= 1)
            ss += __shfl_xor_sync(0xffffffffu, ss, off);
        const float scale = 1.f / fmaxf(sqrtf(ss), EPS_);

        __syncwarp();
        xs[w][lane] = x0; xs[w][lane + 32] = x1;
        __syncwarp();

        float a0 = 0.f, a1 = 0.f;
#pragma unroll
        for (int dd = 0; dd < D_; dd++) {
            const float xv = xs[w][dd];               // broadcast
            a0 = fmaf(xv, rm_s[lane][dd],      a0);
            a1 = fmaf(xv, rm_s[lane + 32][dd], a1);
        }
        a0 *= scale; a1 *= scale;

        float s0, c0, s1, c1;
        sincosf(a0, &s0, &c0);
        sincosf(a1, &s1, &c1);

        float* o = dst + ((size_t)r * H_ + h) * K2_;
        const float sc = 0.125f;   // P^{-1/2}
        o[lane]      = s0 * sc;  o[lane + 32] = s1 * sc;
        o[64 + lane] = c0 * sc;  o[96 + lane] = c1 * sc;
    }
}

// ---------------------------------------------------------------------------
// Causal scan.  One block per (b,h); 512 threads = 16 warps.
// Warp w: c = w&7 owns k in [c*16, c*16+16); dh = w>>3; lane -> d = dh*32+lane.
// S[k][d] in registers (16/thread).
// qz (denominator) is computed ONLY by warps 14-15 (z replicated per-lane
// there), which also write the output; those warps are highest-wid so the
// hi-wid-first arbiter issues them first each step.
// Single __syncthreads per step (double-buffered staging + partials).
// ---------------------------------------------------------------------------
__global__ __launch_bounds__(512)
void scan_kernel()
{
    __shared__ float pk_s[2][K2_], pq_s[2][K2_], v_s[2][D_];
    __shared__ float qsp[2][8][64];

    const int tid  = threadIdx.x;
    const int lane = tid & 31;
    const int w    = tid >> 5;
    const int c    = w & 7;
    const int dh   = w >> 3;
    const int d    = dh * 32 + lane;
    const int bh   = blockIdx.x;
    const int b    = bh >> 3;
    const int h    = bh & 7;

    const bool qzw = (w >= 14);              // warps 14,15 own qz + output
    const int  od  = (w - 14) * 32 + lane;   // output d index for qz warps

    float S[16];
#pragma unroll
    for (int i = 0; i < 16; i++) S[i] = 0.f;
    float z0 = 0.f, z1 = 0.f, z2 = 0.f, z3 = 0.f;

    // preload t = 0
    if (tid < 128)
        pk_s[0][tid]       = g_pk[((size_t)(0 * B_ + b) * H_ + h) * K2_ + tid];
    else if (tid < 256)
        pq_s[0][tid - 128] = g_pq[((size_t)(0 * B_ + b) * H_ + h) * K2_ + tid - 128];
    else if (tid < 320)
        v_s[0][tid - 256]  = g_v[(size_t)(0 * B_ + b) * E_ + h * D_ + tid - 256];
    __syncthreads();

    for (int t = 0; t < T_; t++) {
        const int p = t & 1;

        // denominator: only warps 14-15 (replicated across their lanes)
        float qz = 0.f;
        if (qzw) {
            const float4 pk4 = *(const float4*)&pk_s[p][lane * 4];
            const float4 pq4 = *(const float4*)&pq_s[p][lane * 4];
            z0 += pk4.x; z1 += pk4.y; z2 += pk4.z; z3 += pk4.w;
            qz = pq4.x * z0 + pq4.y * z1 + pq4.z * z2 + pq4.w * z3;
#pragma unroll
            for (int off = 16; off; off >>= 1)
                qz += __shfl_xor_sync(0xffffffffu, qz, off);
        }

        // S update + numerator partial (all phi reads are warp-broadcast).
        // Two qs accumulators shorten the dependent FMA chain.
        const float vd = v_s[p][d];
        const float4* pkb = (const float4*)&pk_s[p][c * 16];
        const float4* pqb = (const float4*)&pq_s[p][c * 16];
        float qsA = 0.f, qsB = 0.f;
#pragma unroll
        for (int j = 0; j < 4; j++) {
            const float4 pk = pkb[j];
            const float4 pq = pqb[j];
            S[4*j+0] = fmaf(pk.x, vd, S[4*j+0]); qsA = fmaf(pq.x, S[4*j+0], qsA);
            S[4*j+1] = fmaf(pk.y, vd, S[4*j+1]); qsB = fmaf(pq.y, S[4*j+1], qsB);
            S[4*j+2] = fmaf(pk.z, vd, S[4*j+2]); qsA = fmaf(pq.z, S[4*j+2], qsA);
            S[4*j+3] = fmaf(pk.w, vd, S[4*j+3]); qsB = fmaf(pq.w, S[4*j+3], qsB);
        }
        qsp[p][c][d] = qsA + qsB;

        // stage t+1 into the other buffer (warps 0-9)
        if (t + 1 < T_) {
            const int np = p ^ 1;
            if (tid < 128)
                pk_s[np][tid]       = g_pk[((size_t)((t+1) * B_ + b) * H_ + h) * K2_ + tid];
            else if (tid < 256)
                pq_s[np][tid - 128] = g_pq[((size_t)((t+1) * B_ + b) * H_ + h) * K2_ + tid - 128];
            else if (tid < 320)
                v_s[np][tid - 256]  = g_v[(size_t)((t+1) * B_ + b) * E_ + h * D_ + tid - 256];
        }
        __syncthreads();

        // finalize (warps 14-15): reduce 8 partials per d, divide, store
        if (qzw) {
            float s = 0.f;
#pragma unroll
            for (int cc = 0; cc < 8; cc++) s += qsp[p][cc][od];
            g_attn[(size_t)(t * B_ + b) * E_ + h * D_ + od] = s / fmaxf(qz, EPS_);
        }
    }
}

// ---------------------------------------------------------------------------
// Launch
// ---------------------------------------------------------------------------
extern "C" void kernel_launch(void* const* d_in, const int* in_sizes, int n_in,
                              void* d_out, int out_size)
{
    (void)in_sizes; (void)n_in; (void)out_size;
    const float* x  = (const float*)d_in[0];
    const float* rm = (const float*)d_in[1];
    const float* Wq = (const float*)d_in[2];
    const float* bq = (const float*)d_in[3];
    const float* Wk = (const float*)d_in[4];
    const float* bk = (const float*)d_in[5];
    const float* Wv = (const float*)d_in[6];
    const float* bv = (const float*)d_in[7];
    const float* Wo = (const float*)d_in[8];
    const float* bo = (const float*)d_in[9];
    float* out = (float*)d_out;

    float *pq_, *pk_, *pv_, *pattn;
    cudaGetSymbolAddress((void**)&pq_,   g_q);
    cudaGetSymbolAddress((void**)&pk_,   g_k);
    cudaGetSymbolAddress((void**)&pv_,   g_v);
    cudaGetSymbolAddress((void**)&pattn, g_attn);

    // Fused QKV: one launch, 384 CTAs
    dim3 qkv_grid(M_ / 128, E_ / 128, 3);   // (32, 4, 3)
    gemm_bias_kernel<<<qkv_grid, 256>>>(x, Wq, Wk, Wv, bq, bk, bv, pq_, pk_, pv_);

    // Fused phi for q and k: one launch
    dim3 pgrid(M_ / 64, H_, 2);             // (64, 8, 2)
    phi_kernel<<<pgrid, 256>>>(rm);

    scan_kernel<<<B_ * H_, 512>>>();

    // Output projection
    dim3 ogrid(M_ / 128, E_ / 128, 1);
    gemm_bias_kernel<<<ogrid, 256>>>(pattn, Wo, Wo, Wo, bo, bo, bo, out, out, out);
}

// round 6
// speedup vs baseline: 2.3711x; 2.3711x over previous
#include <cuda_runtime.h>
#include <math.h>

// Problem constants
#define T_   1024
#define B_   4
#define E_   512
#define H_   8
#define D_   64
#define P_   64
#define K2_  128          // 2*P
#define M_   (T_*B_)      // 4096 rows
#define EPS_ 1e-6f
#define CC_  64           // chunk length
#define NC_  (T_/CC_)     // 16 chunks
#define BH_  (B_*H_)      // 32

// ---------------------------------------------------------------------------
// Static device scratch (no allocations allowed)
// ---------------------------------------------------------------------------
__device__ float g_q    [M_ * E_];          // 8 MB
__device__ float g_k    [M_ * E_];          // 8 MB
__device__ float g_v    [M_ * E_];          // 8 MB
__device__ float g_pq   [M_ * H_ * K2_];    // 16 MB
__device__ float g_pk   [M_ * H_ * K2_];    // 16 MB
__device__ float g_attn [M_ * E_];          // 8 MB
__device__ float g_Ssum [NC_ * BH_ * K2_ * D_];  // 16 MB (chunk states -> exclusive prefix)
__device__ float g_zsum [NC_ * BH_ * K2_];       // 256 KB

// ---------------------------------------------------------------------------
// Packed f32x2 helpers (Blackwell sm_103a)
// ---------------------------------------------------------------------------
__device__ __forceinline__ unsigned long long pack_f32x2(float lo, float hi) {
    unsigned long long r;
    asm("mov.b64 %0, {%1, %2};" : "=l"(r) : "f"(lo), "f"(hi));
    return r;
}
__device__ __forceinline__ void unpack_f32x2(float& lo, float& hi, unsigned long long v) {
    asm("mov.b64 {%0, %1}, %2;" : "=f"(lo), "=f"(hi) : "l"(v));
}
__device__ __forceinline__ unsigned long long fma_f32x2(unsigned long long a,
                                                        unsigned long long b,
                                                        unsigned long long c) {
    unsigned long long d;
    asm("fma.rn.f32x2 %0, %1, %2, %3;" : "=l"(d) : "l"(a), "l"(b), "l"(c));
    return d;
}

// ---------------------------------------------------------------------------
// GEMM with bias: C[M,N] = A[M,K] @ W[N,K]^T + bias[N]   (measured R4: 58.4us
// at fma=45.7% ~= FFMA2 pipe roofline for this shape).
// ---------------------------------------------------------------------------
__global__ __launch_bounds__(256)
void gemm_bias_kernel(const float* __restrict__ A,
                      const float* __restrict__ W0, const float* __restrict__ W1,
                      const float* __restrict__ W2,
                      const float* __restrict__ b0p, const float* __restrict__ b1p,
                      const float* __restrict__ b2p,
                      float* __restrict__ C0, float* __restrict__ C1,
                      float* __restrict__ C2)
{
    constexpr int Kd = 512, BM = 128, BK = 16;
    __shared__ float As[BK][BM + 4];
    __shared__ float Bs[BK][BM + 4];

    const int z = blockIdx.z;
    const float* Bw   = (z == 0) ? W0  : (z == 1) ? W1  : W2;
    const float* bias = (z == 0) ? b0p : (z == 1) ? b1p : b2p;
    float*       C    = (z == 0) ? C0  : (z == 1) ? C1  : C2;

    const int tid  = threadIdx.x;
    const int bm   = blockIdx.x * BM;
    const int bn   = blockIdx.y * BM;
    const int lrow = tid >> 2;
    const int lcol = (tid & 3) << 2;
    const int tx   = tid & 15;
    const int ty   = tid >> 4;

    const float* Ap0 = A  + (size_t)(bm + lrow     ) * Kd + lcol;
    const float* Ap1 = A  + (size_t)(bm + lrow + 64) * Kd + lcol;
    const float* Wp0 = Bw + (size_t)(bn + lrow     ) * Kd + lcol;
    const float* Wp1 = Bw + (size_t)(bn + lrow + 64) * Kd + lcol;

    unsigned long long acc2[8][4];
#pragma unroll
    for (int i = 0; i < 8; i++)
#pragma unroll
        for (int j = 0; j < 4; j++) acc2[i][j] = 0ull;

    float4 ra0 = *(const float4*)(Ap0);
    float4 ra1 = *(const float4*)(Ap1);
    float4 rw0 = *(const float4*)(Wp0);
    float4 rw1 = *(const float4*)(Wp1);

    for (int k0 = 0; k0 < Kd; k0 += BK) {
        __syncthreads();
        As[lcol + 0][lrow]      = ra0.x; As[lcol + 1][lrow]      = ra0.y;
        As[lcol + 2][lrow]      = ra0.z; As[lcol + 3][lrow]      = ra0.w;
        As[lcol + 0][lrow + 64] = ra1.x; As[lcol + 1][lrow + 64] = ra1.y;
        As[lcol + 2][lrow + 64] = ra1.z; As[lcol + 3][lrow + 64] = ra1.w;
        Bs[lcol + 0][lrow]      = rw0.x; Bs[lcol + 1][lrow]      = rw0.y;
        Bs[lcol + 2][lrow]      = rw0.z; Bs[lcol + 3][lrow]      = rw0.w;
        Bs[lcol + 0][lrow + 64] = rw1.x; Bs[lcol + 1][lrow + 64] = rw1.y;
        Bs[lcol + 2][lrow + 64] = rw1.z; Bs[lcol + 3][lrow + 64] = rw1.w;
        __syncthreads();

        if (k0 + BK < Kd) {
            const int kn = k0 + BK;
            ra0 = *(const float4*)(Ap0 + kn);
            ra1 = *(const float4*)(Ap1 + kn);
            rw0 = *(const float4*)(Wp0 + kn);
            rw1 = *(const float4*)(Wp1 + kn);
        }

#pragma unroll
        for (int kk = 0; kk < BK; kk++) {
            float a[8];
            *(float4*)(a)     = *(const float4*)&As[kk][ty * 8];
            *(float4*)(a + 4) = *(const float4*)&As[kk][ty * 8 + 4];
            ulonglong2 bp01 = *(const ulonglong2*)&Bs[kk][tx * 8];
            ulonglong2 bp23 = *(const ulonglong2*)&Bs[kk][tx * 8 + 4];
            unsigned long long bp[4] = { bp01.x, bp01.y, bp23.x, bp23.y };
#pragma unroll
            for (int i = 0; i < 8; i++) {
                const unsigned long long ap = pack_f32x2(a[i], a[i]);
#pragma unroll
                for (int j = 0; j < 4; j++)
                    acc2[i][j] = fma_f32x2(ap, bp[j], acc2[i][j]);
            }
        }
    }

    float bb[8];
#pragma unroll
    for (int j = 0; j < 8; j++) bb[j] = bias[bn + tx * 8 + j];

#pragma unroll
    for (int i = 0; i < 8; i++) {
        float o[8];
#pragma unroll
        for (int j = 0; j < 4; j++)
            unpack_f32x2(o[2 * j], o[2 * j + 1], acc2[i][j]);
#pragma unroll
        for (int j = 0; j < 8; j++) o[j] += bb[j];
        float* cp = C + (size_t)(bm + ty * 8 + i) * 512 + bn + tx * 8;
        *(float4*)cp       = make_float4(o[0], o[1], o[2], o[3]);
        *(float4*)(cp + 4) = make_float4(o[4], o[5], o[6], o[7]);
    }
}

// ---------------------------------------------------------------------------
// phi: [M,H,D] -> [M,H,2P].  grid (M/64, H, 2): z selects q->pq / k->pk.
// ---------------------------------------------------------------------------
__global__ __launch_bounds__(256)
void phi_kernel(const float* __restrict__ rm)
{
    __shared__ float rm_s[P_][D_ + 1];
    __shared__ float xs[8][D_];

    const int tid = threadIdx.x;
    const int h   = blockIdx.y;
    const float* src = (blockIdx.z == 0) ? g_q  : g_k;
    float*       dst = (blockIdx.z == 0) ? g_pq : g_pk;

    for (int i = tid; i < P_ * D_; i += 256)
        rm_s[i >> 6][i & 63] = rm[(size_t)h * P_ * D_ + i];
    __syncthreads();

    const int w    = tid >> 5;
    const int lane = tid & 31;
    const int base = blockIdx.x * 64;

    for (int it = 0; it < 8; it++) {
        const int r = base + it * 8 + w;
        const float* xr = src + ((size_t)r * H_ + h) * D_;
        float x0 = xr[lane], x1 = xr[lane + 32];

        float ss = x0 * x0 + x1 * x1;
#pragma unroll
        for (int off = 16; off; off >>= 1)
            ss += __shfl_xor_sync(0xffffffffu, ss, off);
        const float scale = 1.f / fmaxf(sqrtf(ss), EPS_);

        __syncwarp();
        xs[w][lane] = x0; xs[w][lane + 32] = x1;
        __syncwarp();

        float a0 = 0.f, a1 = 0.f;
#pragma unroll
        for (int dd = 0; dd < D_; dd++) {
            const float xv = xs[w][dd];
            a0 = fmaf(xv, rm_s[lane][dd],      a0);
            a1 = fmaf(xv, rm_s[lane + 32][dd], a1);
        }
        a0 *= scale; a1 *= scale;

        float s0, c0, s1, c1;
        sincosf(a0, &s0, &c0);
        sincosf(a1, &s1, &c1);

        float* o = dst + ((size_t)r * H_ + h) * K2_;
        const float sc = 0.125f;   // P^{-1/2}
        o[lane]      = s0 * sc;  o[lane + 32] = s1 * sc;
        o[64 + lane] = c0 * sc;  o[96 + lane] = c1 * sc;
    }
}

// ---------------------------------------------------------------------------
// S1: per-chunk states.  grid (NC_, BH_), 256 threads.
// Ssum[c][bh][k][d] = sum_{t in chunk} phi_k[t][k] * v[t][d]
// zsum[c][bh][k]    = sum_{t in chunk} phi_k[t][k]
// ---------------------------------------------------------------------------
__global__ __launch_bounds__(256)
void chunk_state_kernel()
{
    __shared__ float pk_s[32 * 128];   // 16 KB
    __shared__ float v_s [32 * 64];    //  8 KB

    const int tid = threadIdx.x;
    const int c   = blockIdx.x;
    const int bh  = blockIdx.y;
    const int b   = bh >> 3;
    const int h   = bh & 7;
    const int tx  = tid & 15;          // d group: d0 = tx*4
    const int ty  = tid >> 4;          // k group: k0 = ty*8
    const int d0  = tx * 4;
    const int k0  = ty * 8;

    float acc[8][4];
#pragma unroll
    for (int i = 0; i < 8; i++)
#pragma unroll
        for (int j = 0; j < 4; j++) acc[i][j] = 0.f;
    float zacc[8];
#pragma unroll
    for (int i = 0; i < 8; i++) zacc[i] = 0.f;

    for (int tb = 0; tb < 2; tb++) {
        __syncthreads();
        {   // load 32 rows of phi_k (32*128 = 4096 el, 16/thread)
            const int t  = tid >> 3;
            const int kk = (tid & 7) * 16;
            const float* src = g_pk +
                ((size_t)((c * CC_ + tb * 32 + t) * B_ + b) * H_ + h) * K2_ + kk;
            float* dstp = &pk_s[t * 128 + kk];
#pragma unroll
            for (int i = 0; i < 16; i += 4)
                *(float4*)(dstp + i) = *(const float4*)(src + i);
        }
        {   // load 32 rows of v (32*64 = 2048 el, 8/thread)
            const int t  = tid >> 3;
            const int dd = (tid & 7) * 8;
            const float* src = g_v +
                (size_t)((c * CC_ + tb * 32 + t) * B_ + b) * E_ + h * D_ + dd;
            float* dstp = &v_s[t * 64 + dd];
#pragma unroll
            for (int i = 0; i < 8; i += 4)
                *(float4*)(dstp + i) = *(const float4*)(src + i);
        }
        __syncthreads();

        for (int t = 0; t < 32; t++) {
            float a[8];
            *(float4*)(a)     = *(const float4*)&pk_s[t * 128 + k0];
            *(float4*)(a + 4) = *(const float4*)&pk_s[t * 128 + k0 + 4];
            const float4 vv = *(const float4*)&v_s[t * 64 + d0];
#pragma unroll
            for (int i = 0; i < 8; i++) {
                acc[i][0] = fmaf(a[i], vv.x, acc[i][0]);
                acc[i][1] = fmaf(a[i], vv.y, acc[i][1]);
                acc[i][2] = fmaf(a[i], vv.z, acc[i][2]);
                acc[i][3] = fmaf(a[i], vv.w, acc[i][3]);
            }
            if (tx == 0) {
#pragma unroll
                for (int i = 0; i < 8; i++) zacc[i] += a[i];
            }
        }
    }

    float* Sout = g_Ssum + (((size_t)c * BH_ + bh) * K2_ + k0) * D_ + d0;
#pragma unroll
    for (int i = 0; i < 8; i++)
        *(float4*)(Sout + (size_t)i * D_) =
            make_float4(acc[i][0], acc[i][1], acc[i][2], acc[i][3]);

    if (tx == 0) {
        float* zout = g_zsum + ((size_t)c * BH_ + bh) * K2_ + k0;
#pragma unroll
        for (int i = 0; i < 8; i++) zout[i] = zacc[i];
    }
}

// ---------------------------------------------------------------------------
// Prefix: in-place EXCLUSIVE prefix over chunks of Ssum and zsum.
// grid (BH_), 256 threads.
// ---------------------------------------------------------------------------
__global__ __launch_bounds__(256)
void chunk_prefix_kernel()
{
    const int tid = threadIdx.x;
    const int bh  = blockIdx.x;

    float run[32];
#pragma unroll
    for (int j = 0; j < 32; j++) run[j] = 0.f;

    for (int c = 0; c < NC_; c++) {
        float* base = g_Ssum + ((size_t)c * BH_ + bh) * (K2_ * D_);
#pragma unroll
        for (int j = 0; j < 32; j++) {
            const int e = j * 256 + tid;
            const float v = base[e];
            base[e] = run[j];
            run[j] += v;
        }
    }

    if (tid < K2_) {
        float rz = 0.f;
        for (int c = 0; c < NC_; c++) {
            float* zp = g_zsum + ((size_t)c * BH_ + bh) * K2_ + tid;
            const float v = *zp;
            *zp = rz;
            rz += v;
        }
    }
}

// ---------------------------------------------------------------------------
// S2: per-chunk output.  grid (NC_, BH_), 256 threads, 48 KB static smem.
//   out[t][d] = ( phi_q[t]·Spre  +  (masked phi_q phi_k^T) @ V )[t][d]
//               / max( phi_q[t]·zpre + rowsum(masked A)[t], EPS )
// smem plan:  sA[8192] = pqT[k][t] (phases 0-II) -> {At[t'][t] | V[t'][d]} (III)
//             sB[4096] = Spre k-tile / pkT k-tile -> zpre[0:128], qzi[128:192],
//                        qz[256:320]
// ---------------------------------------------------------------------------
__global__ __launch_bounds__(256)
void chunk_out_kernel()
{
    __shared__ float sA[8192];
    __shared__ float sB[4096];

    const int tid = threadIdx.x;
    const int c   = blockIdx.x;
    const int bh  = blockIdx.y;
    const int b   = bh >> 3;
    const int h   = bh & 7;
    const int tx  = tid & 15;
    const int ty  = tid >> 4;
    const int t0  = ty * 4;   // output / A row group
    const int d0  = tx * 4;   // output col group
    const int tp0 = tx * 4;   // A col group

    // ---- load pqT[k][t] (transposed phi_q chunk) ----
    {
        const int t     = tid >> 2;
        const int kbase = (tid & 3) * 32;
        const float* src = g_pq +
            ((size_t)((c * CC_ + t) * B_ + b) * H_ + h) * K2_ + kbase;
#pragma unroll
        for (int i = 0; i < 32; i += 4) {
            const float4 v = *(const float4*)(src + i);
            sA[(kbase + i + 0) * 64 + t] = v.x;
            sA[(kbase + i + 1) * 64 + t] = v.y;
            sA[(kbase + i + 2) * 64 + t] = v.z;
            sA[(kbase + i + 3) * 64 + t] = v.w;
        }
    }

    float acc[4][4];
#pragma unroll
    for (int i = 0; i < 4; i++)
#pragma unroll
        for (int j = 0; j < 4; j++) acc[i][j] = 0.f;

    // ---- Phase I: inter-chunk  acc += phi_q @ Spre ----
    for (int kb = 0; kb < 2; kb++) {
        __syncthreads();
        {   // load Spre k-tile [64k][64d] into sB
            const int e = tid * 16;
            const float* sp = g_Ssum +
                (((size_t)c * BH_ + bh) * K2_ + kb * 64) * D_;
#pragma unroll
            for (int i = 0; i < 16; i += 4)
                *(float4*)&sB[e + i] = *(const float4*)(sp + e + i);
        }
        __syncthreads();
        for (int k = 0; k < 64; k++) {
            const float4 a4 = *(const float4*)&sA[(kb * 64 + k) * 64 + t0];
            const float4 b4 = *(const float4*)&sB[k * 64 + d0];
            const float a[4] = { a4.x, a4.y, a4.z, a4.w };
#pragma unroll
            for (int i = 0; i < 4; i++) {
                acc[i][0] = fmaf(a[i], b4.x, acc[i][0]);
                acc[i][1] = fmaf(a[i], b4.y, acc[i][1]);
                acc[i][2] = fmaf(a[i], b4.z, acc[i][2]);
                acc[i][3] = fmaf(a[i], b4.w, acc[i][3]);
            }
        }
    }

    // ---- Phase II: A[t][t'] = phi_q[t] · phi_k[t'] ----
    float Ar[4][4];
#pragma unroll
    for (int i = 0; i < 4; i++)
#pragma unroll
        for (int j = 0; j < 4; j++) Ar[i][j] = 0.f;

    for (int kb = 0; kb < 2; kb++) {
        __syncthreads();
        {   // load pkT k-tile [64k][64t'] into sB (transposed)
            const int t2  = tid >> 2;
            const int kk0 = (tid & 3) * 16;
            const float* src = g_pk +
                ((size_t)((c * CC_ + t2) * B_ + b) * H_ + h) * K2_ + kb * 64 + kk0;
#pragma unroll
            for (int i = 0; i < 16; i += 4) {
                const float4 v = *(const float4*)(src + i);
                sB[(kk0 + i + 0) * 64 + t2] = v.x;
                sB[(kk0 + i + 1) * 64 + t2] = v.y;
                sB[(kk0 + i + 2) * 64 + t2] = v.z;
                sB[(kk0 + i + 3) * 64 + t2] = v.w;
            }
        }
        __syncthreads();
        for (int kk = 0; kk < 64; kk++) {
            const float4 a4 = *(const float4*)&sA[(kb * 64 + kk) * 64 + t0];
            const float4 b4 = *(const float4*)&sB[kk * 64 + tp0];
            const float a[4] = { a4.x, a4.y, a4.z, a4.w };
#pragma unroll
            for (int i = 0; i < 4; i++) {
                Ar[i][0] = fmaf(a[i], b4.x, Ar[i][0]);
                Ar[i][1] = fmaf(a[i], b4.y, Ar[i][1]);
                Ar[i][2] = fmaf(a[i], b4.z, Ar[i][2]);
                Ar[i][3] = fmaf(a[i], b4.w, Ar[i][3]);
            }
        }
    }

    // ---- qz_inter = phi_q · zpre (needs pqT, before it is overwritten) ----
    __syncthreads();
    if (tid < K2_)
        sB[tid] = g_zsum[((size_t)c * BH_ + bh) * K2_ + tid];
    __syncthreads();
    if (tid < 64) {
        float q = 0.f;
        for (int k = 0; k < K2_; k++)
            q = fmaf(sA[k * 64 + tid], sB[k], q);
        sB[128 + tid] = q;
    }
    __syncthreads();

    // ---- write masked A^T into sA[0:4096], load V into sA[4096:8192] ----
#pragma unroll
    for (int i = 0; i < 4; i++)
#pragma unroll
        for (int j = 0; j < 4; j++) {
            const int t  = t0 + i;
            const int tp = tp0 + j;
            sA[tp * 64 + t] = (tp <= t) ? Ar[i][j] : 0.f;
        }
    {
        const int t2  = tid >> 2;
        const int dd0 = (tid & 3) * 16;
        const float* src = g_v +
            (size_t)((c * CC_ + t2) * B_ + b) * E_ + h * D_ + dd0;
#pragma unroll
        for (int i = 0; i < 16; i += 4)
            *(float4*)&sA[4096 + t2 * 64 + dd0 + i] = *(const float4*)(src + i);
    }
    __syncthreads();

    // ---- Phase III: intra  acc += At^T @ V ----
    for (int tp = 0; tp < 64; tp++) {
        const float4 a4 = *(const float4*)&sA[tp * 64 + t0];
        const float4 b4 = *(const float4*)&sA[4096 + tp * 64 + d0];
        const float a[4] = { a4.x, a4.y, a4.z, a4.w };
#pragma unroll
        for (int i = 0; i < 4; i++) {
            acc[i][0] = fmaf(a[i], b4.x, acc[i][0]);
            acc[i][1] = fmaf(a[i], b4.y, acc[i][1]);
            acc[i][2] = fmaf(a[i], b4.z, acc[i][2]);
            acc[i][3] = fmaf(a[i], b4.w, acc[i][3]);
        }
    }

    // ---- qz = max(rowsum(masked A) + qz_inter, EPS) ----
    if (tid < 64) {
        float rs = 0.f;
        for (int tp = 0; tp < 64; tp++)
            rs += sA[tp * 64 + tid];            // masked: zeros above diag
        sB[256 + tid] = fmaxf(rs + sB[128 + tid], EPS_);
    }
    __syncthreads();

    // ---- store ----
#pragma unroll
    for (int i = 0; i < 4; i++) {
        const float inv = 1.f / sB[256 + t0 + i];
        float* op = g_attn +
            (size_t)((c * CC_ + t0 + i) * B_ + b) * E_ + h * D_ + d0;
        *(float4*)op = make_float4(acc[i][0] * inv, acc[i][1] * inv,
                                   acc[i][2] * inv, acc[i][3] * inv);
    }
}

// ---------------------------------------------------------------------------
// Launch
// ---------------------------------------------------------------------------
extern "C" void kernel_launch(void* const* d_in, const int* in_sizes, int n_in,
                              void* d_out, int out_size)
{
    (void)in_sizes; (void)n_in; (void)out_size;
    const float* x  = (const float*)d_in[0];
    const float* rm = (const float*)d_in[1];
    const float* Wq = (const float*)d_in[2];
    const float* bq = (const float*)d_in[3];
    const float* Wk = (const float*)d_in[4];
    const float* bk = (const float*)d_in[5];
    const float* Wv = (const float*)d_in[6];
    const float* bv = (const float*)d_in[7];
    const float* Wo = (const float*)d_in[8];
    const float* bo = (const float*)d_in[9];
    float* out = (float*)d_out;

    float *pq_, *pk_, *pv_, *pattn;
    cudaGetSymbolAddress((void**)&pq_,   g_q);
    cudaGetSymbolAddress((void**)&pk_,   g_k);
    cudaGetSymbolAddress((void**)&pv_,   g_v);
    cudaGetSymbolAddress((void**)&pattn, g_attn);

    // Fused QKV: one launch, 384 CTAs
    dim3 qkv_grid(M_ / 128, E_ / 128, 3);
    gemm_bias_kernel<<<qkv_grid, 256>>>(x, Wq, Wk, Wv, bq, bk, bv, pq_, pk_, pv_);

    // Fused phi for q and k
    dim3 pgrid(M_ / 64, H_, 2);
    phi_kernel<<<pgrid, 256>>>(rm);

    // Chunked linear attention (replaces serial scan)
    dim3 cgrid(NC_, BH_);
    chunk_state_kernel<<<cgrid, 256>>>();
    chunk_prefix_kernel<<<BH_, 256>>>();
    chunk_out_kernel<<<cgrid, 256>>>();

    // Output projection
    dim3 ogrid(M_ / 128, E_ / 128, 1);
    gemm_bias_kernel<<<ogrid, 256>>>(pattn, Wo, Wo, Wo, bo, bo, bo, out, out, out);
}

// round 8
// speedup vs baseline: 2.6075x; 1.0997x over previous
#include <cuda_runtime.h>
#include <math.h>

// Problem constants
#define T_   1024
#define B_   4
#define E_   512
#define H_   8
#define D_   64
#define P_   64
#define K2_  128          // 2*P
#define M_   (T_*B_)      // 4096 rows
#define EPS_ 1e-6f
#define CC_  64           // chunk length
#define NC_  (T_/CC_)     // 16 chunks
#define BH_  (B_*H_)      // 32

// ---------------------------------------------------------------------------
// Static device scratch (no allocations allowed)
// ---------------------------------------------------------------------------
__device__ float g_q    [M_ * E_];          // 8 MB
__device__ float g_k    [M_ * E_];          // 8 MB
__device__ float g_v    [M_ * E_];          // 8 MB
__device__ float g_pq   [M_ * H_ * K2_];    // 16 MB
__device__ float g_pk   [M_ * H_ * K2_];    // 16 MB
__device__ float g_attn [M_ * E_];          // 8 MB
__device__ float g_Ssum [NC_ * BH_ * K2_ * D_];  // 16 MB (chunk states -> exclusive prefix)
__device__ float g_zsum [NC_ * BH_ * K2_];       // 256 KB

// ---------------------------------------------------------------------------
// Packed f32x2 helpers (Blackwell sm_103a)
// ---------------------------------------------------------------------------
__device__ __forceinline__ unsigned long long pack_f32x2(float lo, float hi) {
    unsigned long long r;
    asm("mov.b64 %0, {%1, %2};" : "=l"(r) : "f"(lo), "f"(hi));
    return r;
}
__device__ __forceinline__ void unpack_f32x2(float& lo, float& hi, unsigned long long v) {
    asm("mov.b64 {%0, %1}, %2;" : "=f"(lo), "=f"(hi) : "l"(v));
}
__device__ __forceinline__ unsigned long long fma_f32x2(unsigned long long a,
                                                        unsigned long long b,
                                                        unsigned long long c) {
    unsigned long long d;
    asm("fma.rn.f32x2 %0, %1, %2, %3;" : "=l"(d) : "l"(a), "l"(b), "l"(c));
    return d;
}

// ---------------------------------------------------------------------------
// GEMM with bias: C[M,N] = A[M,K] @ W[N,K]^T + bias[N]   (measured R4: 58.4us
// at fma=45.7% ~= FFMA2 issue-bound ceiling for this shape).
// ---------------------------------------------------------------------------
__global__ __launch_bounds__(256)
void gemm_bias_kernel(const float* __restrict__ A,
                      const float* __restrict__ W0, const float* __restrict__ W1,
                      const float* __restrict__ W2,
                      const float* __restrict__ b0p, const float* __restrict__ b1p,
                      const float* __restrict__ b2p,
                      float* __restrict__ C0, float* __restrict__ C1,
                      float* __restrict__ C2)
{
    constexpr int Kd = 512, BM = 128, BK = 16;
    __shared__ float As[BK][BM + 4];
    __shared__ float Bs[BK][BM + 4];

    const int z = blockIdx.z;
    const float* Bw   = (z == 0) ? W0  : (z == 1) ? W1  : W2;
    const float* bias = (z == 0) ? b0p : (z == 1) ? b1p : b2p;
    float*       C    = (z == 0) ? C0  : (z == 1) ? C1  : C2;

    const int tid  = threadIdx.x;
    const int bm   = blockIdx.x * BM;
    const int bn   = blockIdx.y * BM;
    const int lrow = tid >> 2;
    const int lcol = (tid & 3) << 2;
    const int tx   = tid & 15;
    const int ty   = tid >> 4;

    const float* Ap0 = A  + (size_t)(bm + lrow     ) * Kd + lcol;
    const float* Ap1 = A  + (size_t)(bm + lrow + 64) * Kd + lcol;
    const float* Wp0 = Bw + (size_t)(bn + lrow     ) * Kd + lcol;
    const float* Wp1 = Bw + (size_t)(bn + lrow + 64) * Kd + lcol;

    unsigned long long acc2[8][4];
#pragma unroll
    for (int i = 0; i < 8; i++)
#pragma unroll
        for (int j = 0; j < 4; j++) acc2[i][j] = 0ull;

    float4 ra0 = *(const float4*)(Ap0);
    float4 ra1 = *(const float4*)(Ap1);
    float4 rw0 = *(const float4*)(Wp0);
    float4 rw1 = *(const float4*)(Wp1);

    for (int k0 = 0; k0 < Kd; k0 += BK) {
        __syncthreads();
        As[lcol + 0][lrow]      = ra0.x; As[lcol + 1][lrow]      = ra0.y;
        As[lcol + 2][lrow]      = ra0.z; As[lcol + 3][lrow]      = ra0.w;
        As[lcol + 0][lrow + 64] = ra1.x; As[lcol + 1][lrow + 64] = ra1.y;
        As[lcol + 2][lrow + 64] = ra1.z; As[lcol + 3][lrow + 64] = ra1.w;
        Bs[lcol + 0][lrow]      = rw0.x; Bs[lcol + 1][lrow]      = rw0.y;
        Bs[lcol + 2][lrow]      = rw0.z; Bs[lcol + 3][lrow]      = rw0.w;
        Bs[lcol + 0][lrow + 64] = rw1.x; Bs[lcol + 1][lrow + 64] = rw1.y;
        Bs[lcol + 2][lrow + 64] = rw1.z; Bs[lcol + 3][lrow + 64] = rw1.w;
        __syncthreads();

        if (k0 + BK < Kd) {
            const int kn = k0 + BK;
            ra0 = *(const float4*)(Ap0 + kn);
            ra1 = *(const float4*)(Ap1 + kn);
            rw0 = *(const float4*)(Wp0 + kn);
            rw1 = *(const float4*)(Wp1 + kn);
        }

#pragma unroll
        for (int kk = 0; kk < BK; kk++) {
            float a[8];
            *(float4*)(a)     = *(const float4*)&As[kk][ty * 8];
            *(float4*)(a + 4) = *(const float4*)&As[kk][ty * 8 + 4];
            ulonglong2 bp01 = *(const ulonglong2*)&Bs[kk][tx * 8];
            ulonglong2 bp23 = *(const ulonglong2*)&Bs[kk][tx * 8 + 4];
            unsigned long long bp[4] = { bp01.x, bp01.y, bp23.x, bp23.y };
#pragma unroll
            for (int i = 0; i < 8; i++) {
                const unsigned long long ap = pack_f32x2(a[i], a[i]);
#pragma unroll
                for (int j = 0; j < 4; j++)
                    acc2[i][j] = fma_f32x2(ap, bp[j], acc2[i][j]);
            }
        }
    }

    float bb[8];
#pragma unroll
    for (int j = 0; j < 8; j++) bb[j] = bias[bn + tx * 8 + j];

#pragma unroll
    for (int i = 0; i < 8; i++) {
        float o[8];
#pragma unroll
        for (int j = 0; j < 4; j++)
            unpack_f32x2(o[2 * j], o[2 * j + 1], acc2[i][j]);
#pragma unroll
        for (int j = 0; j < 8; j++) o[j] += bb[j];
        float* cp = C + (size_t)(bm + ty * 8 + i) * 512 + bn + tx * 8;
        *(float4*)cp       = make_float4(o[0], o[1], o[2], o[3]);
        *(float4*)(cp + 4) = make_float4(o[4], o[5], o[6], o[7]);
    }
}

// ---------------------------------------------------------------------------
// phi: [M,H,D] -> [M,H,2P].  grid (M/64, H, 2): z selects q->pq / k->pk.
// ---------------------------------------------------------------------------
__global__ __launch_bounds__(256)
void phi_kernel(const float* __restrict__ rm)
{
    __shared__ float rm_s[P_][D_ + 1];
    __shared__ float xs[8][D_];

    const int tid = threadIdx.x;
    const int h   = blockIdx.y;
    const float* src = (blockIdx.z == 0) ? g_q  : g_k;
    float*       dst = (blockIdx.z == 0) ? g_pq : g_pk;

    for (int i = tid; i < P_ * D_; i += 256)
        rm_s[i >> 6][i & 63] = rm[(size_t)h * P_ * D_ + i];
    __syncthreads();

    const int w    = tid >> 5;
    const int lane = tid & 31;
    const int base = blockIdx.x * 64;

    for (int it = 0; it < 8; it++) {
        const int r = base + it * 8 + w;
        const float* xr = src + ((size_t)r * H_ + h) * D_;
        float x0 = xr[lane], x1 = xr[lane + 32];

        float ss = x0 * x0 + x1 * x1;
#pragma unroll
        for (int off = 16; off; off >>= 1)
            ss += __shfl_xor_sync(0xffffffffu, ss, off);
        const float scale = 1.f / fmaxf(sqrtf(ss), EPS_);

        __syncwarp();
        xs[w][lane] = x0; xs[w][lane + 32] = x1;
        __syncwarp();

        float a0 = 0.f, a1 = 0.f;
#pragma unroll
        for (int dd = 0; dd < D_; dd++) {
            const float xv = xs[w][dd];
            a0 = fmaf(xv, rm_s[lane][dd],      a0);
            a1 = fmaf(xv, rm_s[lane + 32][dd], a1);
        }
        a0 *= scale; a1 *= scale;

        float s0, c0, s1, c1;
        sincosf(a0, &s0, &c0);
        sincosf(a1, &s1, &c1);

        float* o = dst + ((size_t)r * H_ + h) * K2_;
        const float sc = 0.125f;   // P^{-1/2}
        o[lane]      = s0 * sc;  o[lane + 32] = s1 * sc;
        o[64 + lane] = c0 * sc;  o[96 + lane] = c1 * sc;
    }
}

// ---------------------------------------------------------------------------
// S1: per-chunk states.  grid (NC_, BH_), 256 threads.
// Ssum[c][bh][k][d] = sum_{t in chunk} phi_k[t][k] * v[t][d]
// zsum[c][bh][k]    = sum_{t in chunk} phi_k[t][k]
// ---------------------------------------------------------------------------
__global__ __launch_bounds__(256)
void chunk_state_kernel()
{
    __shared__ float pk_s[32 * 128];   // 16 KB
    __shared__ float v_s [32 * 64];    //  8 KB

    const int tid = threadIdx.x;
    const int c   = blockIdx.x;
    const int bh  = blockIdx.y;
    const int b   = bh >> 3;
    const int h   = bh & 7;
    const int tx  = tid & 15;          // d group: d0 = tx*4
    const int ty  = tid >> 4;          // k group: k0 = ty*8
    const int d0  = tx * 4;
    const int k0  = ty * 8;

    float acc[8][4];
#pragma unroll
    for (int i = 0; i < 8; i++)
#pragma unroll
        for (int j = 0; j < 4; j++) acc[i][j] = 0.f;
    float zacc[8];
#pragma unroll
    for (int i = 0; i < 8; i++) zacc[i] = 0.f;

    for (int tb = 0; tb < 2; tb++) {
        __syncthreads();
        {   // load 32 rows of phi_k (32*128 = 4096 el, 16/thread)
            const int t  = tid >> 3;
            const int kk = (tid & 7) * 16;
            const float* src = g_pk +
                ((size_t)((c * CC_ + tb * 32 + t) * B_ + b) * H_ + h) * K2_ + kk;
            float* dstp = &pk_s[t * 128 + kk];
#pragma unroll
            for (int i = 0; i < 16; i += 4)
                *(float4*)(dstp + i) = *(const float4*)(src + i);
        }
        {   // load 32 rows of v (32*64 = 2048 el, 8/thread)
            const int t  = tid >> 3;
            const int dd = (tid & 7) * 8;
            const float* src = g_v +
                (size_t)((c * CC_ + tb * 32 + t) * B_ + b) * E_ + h * D_ + dd;
            float* dstp = &v_s[t * 64 + dd];
#pragma unroll
            for (int i = 0; i < 8; i += 4)
                *(float4*)(dstp + i) = *(const float4*)(src + i);
        }
        __syncthreads();

        for (int t = 0; t < 32; t++) {
            float a[8];
            *(float4*)(a)     = *(const float4*)&pk_s[t * 128 + k0];
            *(float4*)(a + 4) = *(const float4*)&pk_s[t * 128 + k0 + 4];
            const float4 vv = *(const float4*)&v_s[t * 64 + d0];
#pragma unroll
            for (int i = 0; i < 8; i++) {
                acc[i][0] = fmaf(a[i], vv.x, acc[i][0]);
                acc[i][1] = fmaf(a[i], vv.y, acc[i][1]);
                acc[i][2] = fmaf(a[i], vv.z, acc[i][2]);
                acc[i][3] = fmaf(a[i], vv.w, acc[i][3]);
            }
            if (tx == 0) {
#pragma unroll
                for (int i = 0; i < 8; i++) zacc[i] += a[i];
            }
        }
    }

    float* Sout = g_Ssum + (((size_t)c * BH_ + bh) * K2_ + k0) * D_ + d0;
#pragma unroll
    for (int i = 0; i < 8; i++)
        *(float4*)(Sout + (size_t)i * D_) =
            make_float4(acc[i][0], acc[i][1], acc[i][2], acc[i][3]);

    if (tx == 0) {
        float* zout = g_zsum + ((size_t)c * BH_ + bh) * K2_ + k0;
#pragma unroll
        for (int i = 0; i < 8; i++) zout[i] = zacc[i];
    }
}

// ---------------------------------------------------------------------------
// Prefix: in-place EXCLUSIVE prefix over chunks of Ssum and zsum.
// grid (33, BH_): slice s<32 owns elements [s*256, s*256+256) of the
// K2*D = 8192 state plane of bh (one element per thread, 16-step running
// sum in a register); slice 32 (tid<128) owns the zsum plane.
// 1056 CTAs -> full chip; pure streaming of 32 MB.
// ---------------------------------------------------------------------------
__global__ __launch_bounds__(256)
void chunk_prefix_kernel()
{
    const int tid = threadIdx.x;
    const int sl  = blockIdx.x;
    const int bh  = blockIdx.y;

    if (sl < 32) {
        const int e = sl * 256 + tid;
        float run = 0.f;
#pragma unroll
        for (int c = 0; c < NC_; c++) {
            float* p = g_Ssum + ((size_t)c * BH_ + bh) * (K2_ * D_) + e;
            const float v = *p;
            *p = run;
            run += v;
        }
    } else if (tid < K2_) {
        float rz = 0.f;
#pragma unroll
        for (int c = 0; c < NC_; c++) {
            float* zp = g_zsum + ((size_t)c * BH_ + bh) * K2_ + tid;
            const float v = *zp;
            *zp = rz;
            rz += v;
        }
    }
}

// ---------------------------------------------------------------------------
// S2: per-chunk output.  grid (NC_, BH_), 256 threads, 48 KB static smem.
//   out[t][d] = ( phi_q[t]·Spre  +  (masked phi_q phi_k^T) @ V )[t][d]
//               / max( phi_q[t]·zpre + rowsum(masked A)[t], EPS )
// ---------------------------------------------------------------------------
__global__ __launch_bounds__(256)
void chunk_out_kernel()
{
    __shared__ float sA[8192];
    __shared__ float sB[4096];

    const int tid = threadIdx.x;
    const int c   = blockIdx.x;
    const int bh  = blockIdx.y;
    const int b   = bh >> 3;
    const int h   = bh & 7;
    const int tx  = tid & 15;
    const int ty  = tid >> 4;
    const int t0  = ty * 4;   // output / A row group
    const int d0  = tx * 4;   // output col group
    const int tp0 = tx * 4;   // A col group

    // ---- load pqT[k][t] (transposed phi_q chunk) ----
    {
        const int t     = tid >> 2;
        const int kbase = (tid & 3) * 32;
        const float* src = g_pq +
            ((size_t)((c * CC_ + t) * B_ + b) * H_ + h) * K2_ + kbase;
#pragma unroll
        for (int i = 0; i < 32; i += 4) {
            const float4 v = *(const float4*)(src + i);
            sA[(kbase + i + 0) * 64 + t] = v.x;
            sA[(kbase + i + 1) * 64 + t] = v.y;
            sA[(kbase + i + 2) * 64 + t] = v.z;
            sA[(kbase + i + 3) * 64 + t] = v.w;
        }
    }

    float acc[4][4];
#pragma unroll
    for (int i = 0; i < 4; i++)
#pragma unroll
        for (int j = 0; j < 4; j++) acc[i][j] = 0.f;

    // ---- Phase I: inter-chunk  acc += phi_q @ Spre ----
    for (int kb = 0; kb < 2; kb++) {
        __syncthreads();
        {   // load Spre k-tile [64k][64d] into sB
            const int e = tid * 16;
            const float* sp = g_Ssum +
                (((size_t)c * BH_ + bh) * K2_ + kb * 64) * D_;
#pragma unroll
            for (int i = 0; i < 16; i += 4)
                *(float4*)&sB[e + i] = *(const float4*)(sp + e + i);
        }
        __syncthreads();
        for (int k = 0; k < 64; k++) {
            const float4 a4 = *(const float4*)&sA[(kb * 64 + k) * 64 + t0];
            const float4 b4 = *(const float4*)&sB[k * 64 + d0];
            const float a[4] = { a4.x, a4.y, a4.z, a4.w };
#pragma unroll
            for (int i = 0; i < 4; i++) {
                acc[i][0] = fmaf(a[i], b4.x, acc[i][0]);
                acc[i][1] = fmaf(a[i], b4.y, acc[i][1]);
                acc[i][2] = fmaf(a[i], b4.z, acc[i][2]);
                acc[i][3] = fmaf(a[i], b4.w, acc[i][3]);
            }
        }
    }

    // ---- Phase II: A[t][t'] = phi_q[t] · phi_k[t'] ----
    float Ar[4][4];
#pragma unroll
    for (int i = 0; i < 4; i++)
#pragma unroll
        for (int j = 0; j < 4; j++) Ar[i][j] = 0.f;

    for (int kb = 0; kb < 2; kb++) {
        __syncthreads();
        {   // load pkT k-tile [64k][64t'] into sB (transposed)
            const int t2  = tid >> 2;
            const int kk0 = (tid & 3) * 16;
            const float* src = g_pk +
                ((size_t)((c * CC_ + t2) * B_ + b) * H_ + h) * K2_ + kb * 64 + kk0;
#pragma unroll
            for (int i = 0; i < 16; i += 4) {
                const float4 v = *(const float4*)(src + i);
                sB[(kk0 + i + 0) * 64 + t2] = v.x;
                sB[(kk0 + i + 1) * 64 + t2] = v.y;
                sB[(kk0 + i + 2) * 64 + t2] = v.z;
                sB[(kk0 + i + 3) * 64 + t2] = v.w;
            }
        }
        __syncthreads();
        for (int kk = 0; kk < 64; kk++) {
            const float4 a4 = *(const float4*)&sA[(kb * 64 + kk) * 64 + t0];
            const float4 b4 = *(const float4*)&sB[kk * 64 + tp0];
            const float a[4] = { a4.x, a4.y, a4.z, a4.w };
#pragma unroll
            for (int i = 0; i < 4; i++) {
                Ar[i][0] = fmaf(a[i], b4.x, Ar[i][0]);
                Ar[i][1] = fmaf(a[i], b4.y, Ar[i][1]);
                Ar[i][2] = fmaf(a[i], b4.z, Ar[i][2]);
                Ar[i][3] = fmaf(a[i], b4.w, Ar[i][3]);
            }
        }
    }

    // ---- qz_inter = phi_q · zpre (needs pqT, before it is overwritten) ----
    __syncthreads();
    if (tid < K2_)
        sB[tid] = g_zsum[((size_t)c * BH_ + bh) * K2_ + tid];
    __syncthreads();
    if (tid < 64) {
        float q = 0.f;
        for (int k = 0; k < K2_; k++)
            q = fmaf(sA[k * 64 + tid], sB[k], q);
        sB[128 + tid] = q;
    }
    __syncthreads();

    // ---- write masked A^T into sA[0:4096], load V into sA[4096:8192] ----
#pragma unroll
    for (int i = 0; i < 4; i++)
#pragma unroll
        for (int j = 0; j < 4; j++) {
            const int t  = t0 + i;
            const int tp = tp0 + j;
            sA[tp * 64 + t] = (tp <= t) ? Ar[i][j] : 0.f;
        }
    {
        const int t2  = tid >> 2;
        const int dd0 = (tid & 3) * 16;
        const float* src = g_v +
            (size_t)((c * CC_ + t2) * B_ + b) * E_ + h * D_ + dd0;
#pragma unroll
        for (int i = 0; i < 16; i += 4)
            *(float4*)&sA[4096 + t2 * 64 + dd0 + i] = *(const float4*)(src + i);
    }
    __syncthreads();

    // ---- Phase III: intra  acc += At^T @ V ----
    for (int tp = 0; tp < 64; tp++) {
        const float4 a4 = *(const float4*)&sA[tp * 64 + t0];
        const float4 b4 = *(const float4*)&sA[4096 + tp * 64 + d0];
        const float a[4] = { a4.x, a4.y, a4.z, a4.w };
#pragma unroll
        for (int i = 0; i < 4; i++) {
            acc[i][0] = fmaf(a[i], b4.x, acc[i][0]);
            acc[i][1] = fmaf(a[i], b4.y, acc[i][1]);
            acc[i][2] = fmaf(a[i], b4.z, acc[i][2]);
            acc[i][3] = fmaf(a[i], b4.w, acc[i][3]);
        }
    }

    // ---- qz = max(rowsum(masked A) + qz_inter, EPS) ----
    if (tid < 64) {
        float rs = 0.f;
        for (int tp = 0; tp < 64; tp++)
            rs += sA[tp * 64 + tid];            // masked: zeros above diag
        sB[256 + tid] = fmaxf(rs + sB[128 + tid], EPS_);
    }
    __syncthreads();

    // ---- store ----
#pragma unroll
    for (int i = 0; i < 4; i++) {
        const float inv = 1.f / sB[256 + t0 + i];
        float* op = g_attn +
            (size_t)((c * CC_ + t0 + i) * B_ + b) * E_ + h * D_ + d0;
        *(float4*)op = make_float4(acc[i][0] * inv, acc[i][1] * inv,
                                   acc[i][2] * inv, acc[i][3] * inv);
    }
}

// ---------------------------------------------------------------------------
// Launch
// ---------------------------------------------------------------------------
extern "C" void kernel_launch(void* const* d_in, const int* in_sizes, int n_in,
                              void* d_out, int out_size)
{
    (void)in_sizes; (void)n_in; (void)out_size;
    const float* x  = (const float*)d_in[0];
    const float* rm = (const float*)d_in[1];
    const float* Wq = (const float*)d_in[2];
    const float* bq = (const float*)d_in[3];
    const float* Wk = (const float*)d_in[4];
    const float* bk = (const float*)d_in[5];
    const float* Wv = (const float*)d_in[6];
    const float* bv = (const float*)d_in[7];
    const float* Wo = (const float*)d_in[8];
    const float* bo = (const float*)d_in[9];
    float* out = (float*)d_out;

    float *pq_, *pk_, *pv_, *pattn;
    cudaGetSymbolAddress((void**)&pq_,   g_q);
    cudaGetSymbolAddress((void**)&pk_,   g_k);
    cudaGetSymbolAddress((void**)&pv_,   g_v);
    cudaGetSymbolAddress((void**)&pattn, g_attn);

    // Fused QKV: one launch, 384 CTAs
    dim3 qkv_grid(M_ / 128, E_ / 128, 3);
    gemm_bias_kernel<<<qkv_grid, 256>>>(x, Wq, Wk, Wv, bq, bk, bv, pq_, pk_, pv_);

    // Fused phi for q and k
    dim3 pgrid(M_ / 64, H_, 2);
    phi_kernel<<<pgrid, 256>>>(rm);

    // Chunked linear attention
    dim3 cgrid(NC_, BH_);
    chunk_state_kernel<<<cgrid, 256>>>();
    chunk_prefix_kernel<<<dim3(33, BH_), 256>>>();
    chunk_out_kernel<<<cgrid, 256>>>();

    // Output projection
    dim3 ogrid(M_ / 128, E_ / 128, 1);
    gemm_bias_kernel<<<ogrid, 256>>>(pattn, Wo, Wo, Wo, bo, bo, bo, out, out, out);
}

// round 10
// speedup vs baseline: 2.6732x; 1.0252x over previous
#include <cuda_runtime.h>
#include <math.h>

// Problem constants
#define T_   1024
#define B_   4
#define E_   512
#define H_   8
#define D_   64
#define P_   64
#define K2_  128          // 2*P
#define M_   (T_*B_)      // 4096 rows
#define EPS_ 1e-6f
#define CC_  64           // chunk length
#define NC_  (T_/CC_)     // 16 chunks
#define BH_  (B_*H_)      // 32

// ---------------------------------------------------------------------------
// Static device scratch (no allocations allowed)
// ---------------------------------------------------------------------------
__device__ float g_q    [M_ * E_];          // 8 MB
__device__ float g_k    [M_ * E_];          // 8 MB
__device__ float g_v    [M_ * E_];          // 8 MB
__device__ float g_pq   [M_ * H_ * K2_];    // 16 MB
__device__ float g_pk   [M_ * H_ * K2_];    // 16 MB
__device__ float g_attn [M_ * E_];          // 8 MB
__device__ float g_Ssum [NC_ * BH_ * K2_ * D_];  // 16 MB
__device__ float g_zsum [NC_ * BH_ * K2_];       // 256 KB

// ---------------------------------------------------------------------------
// Packed f32x2 helpers (Blackwell sm_103a)
// ---------------------------------------------------------------------------
__device__ __forceinline__ unsigned long long pack_f32x2(float lo, float hi) {
    unsigned long long r;
    asm("mov.b64 %0, {%1, %2};" : "=l"(r) : "f"(lo), "f"(hi));
    return r;
}
__device__ __forceinline__ void unpack_f32x2(float& lo, float& hi, unsigned long long v) {
    asm("mov.b64 {%0, %1}, %2;" : "=f"(lo), "=f"(hi) : "l"(v));
}
__device__ __forceinline__ unsigned long long fma_f32x2(unsigned long long a,
                                                        unsigned long long b,
                                                        unsigned long long c) {
    unsigned long long d;
    asm("fma.rn.f32x2 %0, %1, %2, %3;" : "=l"(d) : "l"(a), "l"(b), "l"(c));
    return d;
}

// ---------------------------------------------------------------------------
// GEMM with bias: C[M,N] = A[M,K] @ W[N,K]^T + bias[N]
// 512 threads, tile 128x128, BK=16, microtile 8x4 (FFMA2-packed).
// R4 profile showed the 256-thread version at occ=12.4% (2 warps/SMSP),
// issue=35.6% -> latency-stalled.  512 threads -> 4 warps/SMSP, ~70 regs.
// blockIdx.z selects (W, bias, C) so QKV runs as ONE launch.
// ---------------------------------------------------------------------------
__global__ __launch_bounds__(512)
void gemm_bias_kernel(const float* __restrict__ A,
                      const float* __restrict__ W0, const float* __restrict__ W1,
                      const float* __restrict__ W2,
                      const float* __restrict__ b0p, const float* __restrict__ b1p,
                      const float* __restrict__ b2p,
                      float* __restrict__ C0, float* __restrict__ C1,
                      float* __restrict__ C2)
{
    constexpr int Kd = 512, BM = 128, BK = 16;
    __shared__ float As[BK][BM + 4];   // row pitch 132 floats = 528 B (16B mult)
    __shared__ float Bs[BK][BM + 4];

    const int z = blockIdx.z;
    const float* Bw   = (z == 0) ? W0  : (z == 1) ? W1  : W2;
    const float* bias = (z == 0) ? b0p : (z == 1) ? b1p : b2p;
    float*       C    = (z == 0) ? C0  : (z == 1) ? C1  : C2;

    const int tid  = threadIdx.x;
    const int bm   = blockIdx.x * BM;
    const int bn   = blockIdx.y * BM;
    const int lrow = tid >> 2;          // 0..127
    const int lcol = (tid & 3) << 2;    // 0,4,8,12
    const int tx   = tid & 31;          // col group: 4 cols
    const int ty   = tid >> 5;          // row group: 8 rows

    const float* Ap = A  + (size_t)(bm + lrow) * Kd + lcol;
    const float* Wp = Bw + (size_t)(bn + lrow) * Kd + lcol;

    // acc2[i][j2] packs output cols (tx*4 + 2*j2, +1) for row ty*8+i
    unsigned long long acc2[8][2];
#pragma unroll
    for (int i = 0; i < 8; i++) { acc2[i][0] = 0ull; acc2[i][1] = 0ull; }

    // prologue prefetch
    float4 ra = *(const float4*)(Ap);
    float4 rw = *(const float4*)(Wp);

    for (int k0 = 0; k0 < Kd; k0 += BK) {
        __syncthreads();
        As[lcol + 0][lrow] = ra.x; As[lcol + 1][lrow] = ra.y;
        As[lcol + 2][lrow] = ra.z; As[lcol + 3][lrow] = ra.w;
        Bs[lcol + 0][lrow] = rw.x; Bs[lcol + 1][lrow] = rw.y;
        Bs[lcol + 2][lrow] = rw.z; Bs[lcol + 3][lrow] = rw.w;
        __syncthreads();

        if (k0 + BK < Kd) {
            ra = *(const float4*)(Ap + k0 + BK);
            rw = *(const float4*)(Wp + k0 + BK);
        }

#pragma unroll
        for (int kk = 0; kk < BK; kk++) {
            float a[8];
            *(float4*)(a)     = *(const float4*)&As[kk][ty * 8];
            *(float4*)(a + 4) = *(const float4*)&As[kk][ty * 8 + 4];
            ulonglong2 bp = *(const ulonglong2*)&Bs[kk][tx * 4];
#pragma unroll
            for (int i = 0; i < 8; i++) {
                const unsigned long long ap = pack_f32x2(a[i], a[i]);
                acc2[i][0] = fma_f32x2(ap, bp.x, acc2[i][0]);
                acc2[i][1] = fma_f32x2(ap, bp.y, acc2[i][1]);
            }
        }
    }

    float bb[4];
#pragma unroll
    for (int j = 0; j < 4; j++) bb[j] = bias[bn + tx * 4 + j];

#pragma unroll
    for (int i = 0; i < 8; i++) {
        float o[4];
        unpack_f32x2(o[0], o[1], acc2[i][0]);
        unpack_f32x2(o[2], o[3], acc2[i][1]);
#pragma unroll
        for (int j = 0; j < 4; j++) o[j] += bb[j];
        float* cp = C + (size_t)(bm + ty * 8 + i) * 512 + bn + tx * 4;
        *(float4*)cp = make_float4(o[0], o[1], o[2], o[3]);
    }
}

// ---------------------------------------------------------------------------
// phi: [M,H,D] -> [M,H,2P].  grid (M/64, H, 2): z selects q->pq / k->pk.
// ---------------------------------------------------------------------------
__global__ __launch_bounds__(256)
void phi_kernel(const float* __restrict__ rm)
{
    __shared__ float rm_s[P_][D_ + 1];
    __shared__ float xs[8][D_];

    const int tid = threadIdx.x;
    const int h   = blockIdx.y;
    const float* src = (blockIdx.z == 0) ? g_q  : g_k;
    float*       dst = (blockIdx.z == 0) ? g_pq : g_pk;

    for (int i = tid; i < P_ * D_; i += 256)
        rm_s[i >> 6][i & 63] = rm[(size_t)h * P_ * D_ + i];
    __syncthreads();

    const int w    = tid >> 5;
    const int lane = tid & 31;
    const int base = blockIdx.x * 64;

    for (int it = 0; it < 8; it++) {
        const int r = base + it * 8 + w;
        const float* xr = src + ((size_t)r * H_ + h) * D_;
        float x0 = xr[lane], x1 = xr[lane + 32];

        float ss = x0 * x0 + x1 * x1;
#pragma unroll
        for (int off = 16; off; off >>= 1)
            ss += __shfl_xor_sync(0xffffffffu, ss, off);
        const float scale = 1.f / fmaxf(sqrtf(ss), EPS_);

        __syncwarp();
        xs[w][lane] = x0; xs[w][lane + 32] = x1;
        __syncwarp();

        float a0 = 0.f, a1 = 0.f;
#pragma unroll
        for (int dd = 0; dd < D_; dd++) {
            const float xv = xs[w][dd];
            a0 = fmaf(xv, rm_s[lane][dd],      a0);
            a1 = fmaf(xv, rm_s[lane + 32][dd], a1);
        }
        a0 *= scale; a1 *= scale;

        float s0, c0, s1, c1;
        sincosf(a0, &s0, &c0);
        sincosf(a1, &s1, &c1);

        float* o = dst + ((size_t)r * H_ + h) * K2_;
        const float sc = 0.125f;   // P^{-1/2}
        o[lane]      = s0 * sc;  o[lane + 32] = s1 * sc;
        o[64 + lane] = c0 * sc;  o[96 + lane] = c1 * sc;
    }
}

// ---------------------------------------------------------------------------
// S1: per-chunk states.  grid (NC_, BH_), 256 threads.
// ---------------------------------------------------------------------------
__global__ __launch_bounds__(256)
void chunk_state_kernel()
{
    __shared__ float pk_s[32 * 128];   // 16 KB
    __shared__ float v_s [32 * 64];    //  8 KB

    const int tid = threadIdx.x;
    const int c   = blockIdx.x;
    const int bh  = blockIdx.y;
    const int b   = bh >> 3;
    const int h   = bh & 7;
    const int tx  = tid & 15;
    const int ty  = tid >> 4;
    const int d0  = tx * 4;
    const int k0  = ty * 8;

    float acc[8][4];
#pragma unroll
    for (int i = 0; i < 8; i++)
#pragma unroll
        for (int j = 0; j < 4; j++) acc[i][j] = 0.f;
    float zacc[8];
#pragma unroll
    for (int i = 0; i < 8; i++) zacc[i] = 0.f;

    for (int tb = 0; tb < 2; tb++) {
        __syncthreads();
        {
            const int t  = tid >> 3;
            const int kk = (tid & 7) * 16;
            const float* src = g_pk +
                ((size_t)((c * CC_ + tb * 32 + t) * B_ + b) * H_ + h) * K2_ + kk;
            float* dstp = &pk_s[t * 128 + kk];
#pragma unroll
            for (int i = 0; i < 16; i += 4)
                *(float4*)(dstp + i) = *(const float4*)(src + i);
        }
        {
            const int t  = tid >> 3;
            const int dd = (tid & 7) * 8;
            const float* src = g_v +
                (size_t)((c * CC_ + tb * 32 + t) * B_ + b) * E_ + h * D_ + dd;
            float* dstp = &v_s[t * 64 + dd];
#pragma unroll
            for (int i = 0; i < 8; i += 4)
                *(float4*)(dstp + i) = *(const float4*)(src + i);
        }
        __syncthreads();

        for (int t = 0; t < 32; t++) {
            float a[8];
            *(float4*)(a)     = *(const float4*)&pk_s[t * 128 + k0];
            *(float4*)(a + 4) = *(const float4*)&pk_s[t * 128 + k0 + 4];
            const float4 vv = *(const float4*)&v_s[t * 64 + d0];
#pragma unroll
            for (int i = 0; i < 8; i++) {
                acc[i][0] = fmaf(a[i], vv.x, acc[i][0]);
                acc[i][1] = fmaf(a[i], vv.y, acc[i][1]);
                acc[i][2] = fmaf(a[i], vv.z, acc[i][2]);
                acc[i][3] = fmaf(a[i], vv.w, acc[i][3]);
            }
            if (tx == 0) {
#pragma unroll
                for (int i = 0; i < 8; i++) zacc[i] += a[i];
            }
        }
    }

    float* Sout = g_Ssum + (((size_t)c * BH_ + bh) * K2_ + k0) * D_ + d0;
#pragma unroll
    for (int i = 0; i < 8; i++)
        *(float4*)(Sout + (size_t)i * D_) =
            make_float4(acc[i][0], acc[i][1], acc[i][2], acc[i][3]);

    if (tx == 0) {
        float* zout = g_zsum + ((size_t)c * BH_ + bh) * K2_ + k0;
#pragma unroll
        for (int i = 0; i < 8; i++) zout[i] = zacc[i];
    }
}

// ---------------------------------------------------------------------------
// Prefix: exclusive prefix over chunks.  grid (33, BH_) — measured 12.6us.
// ---------------------------------------------------------------------------
__global__ __launch_bounds__(256)
void chunk_prefix_kernel()
{
    const int tid = threadIdx.x;
    const int sl  = blockIdx.x;
    const int bh  = blockIdx.y;

    if (sl < 32) {
        const int e = sl * 256 + tid;
        float run = 0.f;
#pragma unroll
        for (int c = 0; c < NC_; c++) {
            float* p = g_Ssum + ((size_t)c * BH_ + bh) * (K2_ * D_) + e;
            const float v = *p;
            *p = run;
            run += v;
        }
    } else if (tid < K2_) {
        float rz = 0.f;
#pragma unroll
        for (int c = 0; c < NC_; c++) {
            float* zp = g_zsum + ((size_t)c * BH_ + bh) * K2_ + tid;
            const float v = *zp;
            *zp = rz;
            rz += v;
        }
    }
}

// ---------------------------------------------------------------------------
// S2: per-chunk output.  grid (NC_, BH_), 256 threads, 48 KB static smem.
// ---------------------------------------------------------------------------
__global__ __launch_bounds__(256)
void chunk_out_kernel()
{
    __shared__ float sA[8192];
    __shared__ float sB[4096];

    const int tid = threadIdx.x;
    const int c   = blockIdx.x;
    const int bh  = blockIdx.y;
    const int b   = bh >> 3;
    const int h   = bh & 7;
    const int tx  = tid & 15;
    const int ty  = tid >> 4;
    const int t0  = ty * 4;
    const int d0  = tx * 4;
    const int tp0 = tx * 4;

    // ---- load pqT[k][t] ----
    {
        const int t     = tid >> 2;
        const int kbase = (tid & 3) * 32;
        const float* src = g_pq +
            ((size_t)((c * CC_ + t) * B_ + b) * H_ + h) * K2_ + kbase;
#pragma unroll
        for (int i = 0; i < 32; i += 4) {
            const float4 v = *(const float4*)(src + i);
            sA[(kbase + i + 0) * 64 + t] = v.x;
            sA[(kbase + i + 1) * 64 + t] = v.y;
            sA[(kbase + i + 2) * 64 + t] = v.z;
            sA[(kbase + i + 3) * 64 + t] = v.w;
        }
    }

    float acc[4][4];
#pragma unroll
    for (int i = 0; i < 4; i++)
#pragma unroll
        for (int j = 0; j < 4; j++) acc[i][j] = 0.f;

    // ---- Phase I: inter-chunk  acc += phi_q @ Spre ----
    for (int kb = 0; kb < 2; kb++) {
        __syncthreads();
        {
            const int e = tid * 16;
            const float* sp = g_Ssum +
                (((size_t)c * BH_ + bh) * K2_ + kb * 64) * D_;
#pragma unroll
            for (int i = 0; i < 16; i += 4)
                *(float4*)&sB[e + i] = *(const float4*)(sp + e + i);
        }
        __syncthreads();
        for (int k = 0; k < 64; k++) {
            const float4 a4 = *(const float4*)&sA[(kb * 64 + k) * 64 + t0];
            const float4 b4 = *(const float4*)&sB[k * 64 + d0];
            const float a[4] = { a4.x, a4.y, a4.z, a4.w };
#pragma unroll
            for (int i = 0; i < 4; i++) {
                acc[i][0] = fmaf(a[i], b4.x, acc[i][0]);
                acc[i][1] = fmaf(a[i], b4.y, acc[i][1]);
                acc[i][2] = fmaf(a[i], b4.z, acc[i][2]);
                acc[i][3] = fmaf(a[i], b4.w, acc[i][3]);
            }
        }
    }

    // ---- Phase II: A[t][t'] = phi_q[t] · phi_k[t'] ----
    float Ar[4][4];
#pragma unroll
    for (int i = 0; i < 4; i++)
#pragma unroll
        for (int j = 0; j < 4; j++) Ar[i][j] = 0.f;

    for (int kb = 0; kb < 2; kb++) {
        __syncthreads();
        {
            const int t2  = tid >> 2;
            const int kk0 = (tid & 3) * 16;
            const float* src = g_pk +
                ((size_t)((c * CC_ + t2) * B_ + b) * H_ + h) * K2_ + kb * 64 + kk0;
#pragma unroll
            for (int i = 0; i < 16; i += 4) {
                const float4 v = *(const float4*)(src + i);
                sB[(kk0 + i + 0) * 64 + t2] = v.x;
                sB[(kk0 + i + 1) * 64 + t2] = v.y;
                sB[(kk0 + i + 2) * 64 + t2] = v.z;
                sB[(kk0 + i + 3) * 64 + t2] = v.w;
            }
        }
        __syncthreads();
        for (int kk = 0; kk < 64; kk++) {
            const float4 a4 = *(const float4*)&sA[(kb * 64 + kk) * 64 + t0];
            const float4 b4 = *(const float4*)&sB[kk * 64 + tp0];
            const float a[4] = { a4.x, a4.y, a4.z, a4.w };
#pragma unroll
            for (int i = 0; i < 4; i++) {
                Ar[i][0] = fmaf(a[i], b4.x, Ar[i][0]);
                Ar[i][1] = fmaf(a[i], b4.y, Ar[i][1]);
                Ar[i][2] = fmaf(a[i], b4.z, Ar[i][2]);
                Ar[i][3] = fmaf(a[i], b4.w, Ar[i][3]);
            }
        }
    }

    // ---- qz_inter = phi_q · zpre ----
    __syncthreads();
    if (tid < K2_)
        sB[tid] = g_zsum[((size_t)c * BH_ + bh) * K2_ + tid];
    __syncthreads();
    if (tid < 64) {
        float q = 0.f;
        for (int k = 0; k < K2_; k++)
            q = fmaf(sA[k * 64 + tid], sB[k], q);
        sB[128 + tid] = q;
    }
    __syncthreads();

    // ---- masked A^T into sA[0:4096], V into sA[4096:8192] ----
#pragma unroll
    for (int i = 0; i < 4; i++)
#pragma unroll
        for (int j = 0; j < 4; j++) {
            const int t  = t0 + i;
            const int tp = tp0 + j;
            sA[tp * 64 + t] = (tp <= t) ? Ar[i][j] : 0.f;
        }
    {
        const int t2  = tid >> 2;
        const int dd0 = (tid & 3) * 16;
        const float* src = g_v +
            (size_t)((c * CC_ + t2) * B_ + b) * E_ + h * D_ + dd0;
#pragma unroll
        for (int i = 0; i < 16; i += 4)
            *(float4*)&sA[4096 + t2 * 64 + dd0 + i] = *(const float4*)(src + i);
    }
    __syncthreads();

    // ---- Phase III: intra  acc += At^T @ V ----
    for (int tp = 0; tp < 64; tp++) {
        const float4 a4 = *(const float4*)&sA[tp * 64 + t0];
        const float4 b4 = *(const float4*)&sA[4096 + tp * 64 + d0];
        const float a[4] = { a4.x, a4.y, a4.z, a4.w };
#pragma unroll
        for (int i = 0; i < 4; i++) {
            acc[i][0] = fmaf(a[i], b4.x, acc[i][0]);
            acc[i][1] = fmaf(a[i], b4.y, acc[i][1]);
            acc[i][2] = fmaf(a[i], b4.z, acc[i][2]);
            acc[i][3] = fmaf(a[i], b4.w, acc[i][3]);
        }
    }

    // ---- qz = max(rowsum(masked A) + qz_inter, EPS) ----
    if (tid < 64) {
        float rs = 0.f;
        for (int tp = 0; tp < 64; tp++)
            rs += sA[tp * 64 + tid];
        sB[256 + tid] = fmaxf(rs + sB[128 + tid], EPS_);
    }
    __syncthreads();

    // ---- store ----
#pragma unroll
    for (int i = 0; i < 4; i++) {
        const float inv = 1.f / sB[256 + t0 + i];
        float* op = g_attn +
            (size_t)((c * CC_ + t0 + i) * B_ + b) * E_ + h * D_ + d0;
        *(float4*)op = make_float4(acc[i][0] * inv, acc[i][1] * inv,
                                   acc[i][2] * inv, acc[i][3] * inv);
    }
}

// ---------------------------------------------------------------------------
// Launch
// ---------------------------------------------------------------------------
extern "C" void kernel_launch(void* const* d_in, const int* in_sizes, int n_in,
                              void* d_out, int out_size)
{
    (void)in_sizes; (void)n_in; (void)out_size;
    const float* x  = (const float*)d_in[0];
    const float* rm = (const float*)d_in[1];
    const float* Wq = (const float*)d_in[2];
    const float* bq = (const float*)d_in[3];
    const float* Wk = (const float*)d_in[4];
    const float* bk = (const float*)d_in[5];
    const float* Wv = (const float*)d_in[6];
    const float* bv = (const float*)d_in[7];
    const float* Wo = (const float*)d_in[8];
    const float* bo = (const float*)d_in[9];
    float* out = (float*)d_out;

    float *pq_, *pk_, *pv_, *pattn;
    cudaGetSymbolAddress((void**)&pq_,   g_q);
    cudaGetSymbolAddress((void**)&pk_,   g_k);
    cudaGetSymbolAddress((void**)&pv_,   g_v);
    cudaGetSymbolAddress((void**)&pattn, g_attn);

    // Fused QKV: one launch, 384 CTAs (512 threads each)
    dim3 qkv_grid(M_ / 128, E_ / 128, 3);
    gemm_bias_kernel<<<qkv_grid, 512>>>(x, Wq, Wk, Wv, bq, bk, bv, pq_, pk_, pv_);

    // Fused phi for q and k
    dim3 pgrid(M_ / 64, H_, 2);
    phi_kernel<<<pgrid, 256>>>(rm);

    // Chunked linear attention
    dim3 cgrid(NC_, BH_);
    chunk_state_kernel<<<cgrid, 256>>>();
    chunk_prefix_kernel<<<dim3(33, BH_), 256>>>();
    chunk_out_kernel<<<cgrid, 256>>>();

    // Output projection
    dim3 ogrid(M_ / 128, E_ / 128, 1);
    gemm_bias_kernel<<<ogrid, 512>>>(pattn, Wo, Wo, Wo, bo, bo, bo, out, out, out);
}